// round 8
// baseline (speedup 1.0000x reference)
#include <cuda_runtime.h>
#include <cstdint>

// Problem constants (fixed shapes from reference):
//   x0:     (B=4, N=512, 3)            float32
//   params: (B=4, T=96, N=512, 514)    float32
// Outputs concatenated into d_out:
//   output_view: (B, T, N, 3)   -> offset 0,           589824 elems
//   epiparams:   (B, T, N, 514) -> offset 589824,      101056512 elems

#define BB 4
#define TT 96
#define NN 512
#define PROW 514
#define EPSV 1e-8f

#define BLOCKS_PER_GROUP 32
#define THREADS 512
#define WARPS 16
#define OUT_VIEW_ELEMS (BB * TT * NN * 3)   // 589824

// ---- global scratch (static device arrays; no allocation) ----
__device__ unsigned g_count[BB];
__device__ unsigned g_release[BB];
__device__ float g_xS[2][BB][NN];
__device__ float g_xI[2][BB][NN];
__device__ float g_xR[2][BB][NN];

__global__ void reset_kernel() {
    if (threadIdx.x < BB) {
        g_count[threadIdx.x]   = 0u;
        g_release[threadIdx.x] = 0u;
    }
}

// Monotonic-epoch inter-block barrier within one b-group (32 blocks).
// epoch starts at 1 and increases each step; counters are reset per replay
// by reset_kernel, so graph replays are deterministic.
__device__ __forceinline__ void group_barrier(int g, unsigned epoch) {
    __syncthreads();
    if (threadIdx.x == 0) {
        __threadfence();
        unsigned arrived = atomicAdd(&g_count[g], 1u) + 1u;
        if (arrived == epoch * (unsigned)BLOCKS_PER_GROUP) {
            atomicExch(&g_release[g], epoch);
        } else {
            while (atomicAdd(&g_release[g], 0u) < epoch) {
                __nanosleep(64);
            }
        }
        __threadfence();
    }
    __syncthreads();
}

__device__ __forceinline__ void load_row(const float* __restrict__ params,
                                         size_t rindex, int lane,
                                         float2 v[8], float& p01) {
    const float* prow = params + rindex * (size_t)PROW;
    p01 = (lane < 2) ? prow[lane] : 0.0f;
    // prow+2 is 8-byte aligned for every row (row stride 514*4 = 2056 B, +8).
    const float2* prow2 = reinterpret_cast<const float2*>(prow + 2);
#pragma unroll
    for (int k = 0; k < 8; ++k) v[k] = prow2[lane + 32 * k];
}

__global__ void __launch_bounds__(THREADS, 1)
ssir_kernel(const float* __restrict__ x0,
            const float* __restrict__ params,
            float* __restrict__ out) {
    __shared__ float I_s[NN];
    float2* I_s2 = reinterpret_cast<float2*>(I_s);

    const int b    = blockIdx.y;
    const int warp = threadIdx.x >> 5;
    const int lane = threadIdx.x & 31;
    const int n    = blockIdx.x * WARPS + warp;  // row handled by this warp

    float* outv = out;                    // output_view region
    float* oute = out + OUT_VIEW_ELEMS;   // epiparams region

    const size_t rbase = ((size_t)b * TT) * NN + (size_t)n;

    // Prefetch t=0 params row into registers.
    float2 v[8];
    float p01;
    load_row(params, rbase, lane, v, p01);

    for (int t = 0; t < TT; ++t) {
        const int par = t & 1;  // state buffer read parity (t=0 reads x0)

        // Stage I_t[b][:] into shared memory (one element per thread).
        if (t == 0) {
            I_s[threadIdx.x] = x0[((size_t)b * NN + threadIdx.x) * 3 + 1];
        } else {
            I_s[threadIdx.x] = g_xI[par][b][threadIdx.x];
        }
        __syncthreads();

        const size_t rindex = rbase + (size_t)t * NN;

        // beta / gamma
        float p0 = __shfl_sync(0xffffffffu, p01, 0);
        float p1 = __shfl_sync(0xffffffffu, p01, 1);
        float beta  = 1.0f / (1.0f + __expf(-p0));
        float gamma = 1.0f / (1.0f + __expf(-p1));

        // Row max
        float m = -1e30f;
#pragma unroll
        for (int k = 0; k < 8; ++k) m = fmaxf(m, fmaxf(v[k].x, v[k].y));
#pragma unroll
        for (int off = 16; off; off >>= 1)
            m = fmaxf(m, __shfl_xor_sync(0xffffffffu, m, off));

        // exp, sum, and fused dot with I
        float sum = 0.0f, dot = 0.0f;
#pragma unroll
        for (int k = 0; k < 8; ++k) {
            float ex = __expf(v[k].x - m);
            float ey = __expf(v[k].y - m);
            float2 iv = I_s2[lane + 32 * k];
            sum += ex + ey;
            dot += ex * iv.x + ey * iv.y;
            v[k].x = ex;
            v[k].y = ey;
        }
#pragma unroll
        for (int off = 16; off; off >>= 1) {
            sum += __shfl_xor_sync(0xffffffffu, sum, off);
            dot += __shfl_xor_sync(0xffffffffu, dot, off);
        }
        float inv = 1.0f / sum;
        float infection = dot * inv;

        // Write epiparams row: [beta, gamma, softmax...]
        float* erow = oute + rindex * (size_t)PROW;
        if (lane == 0)
            *reinterpret_cast<float2*>(erow) = make_float2(beta, gamma);
        float2* erow2 = reinterpret_cast<float2*>(erow + 2);
#pragma unroll
        for (int k = 0; k < 8; ++k)
            erow2[lane + 32 * k] = make_float2(v[k].x * inv, v[k].y * inv);

        // State update (all lanes compute redundantly; lane 0 writes state)
        float S, R;
        if (t == 0) {
            const float* xr = x0 + ((size_t)b * NN + n) * 3;
            S = xr[0];
            R = xr[2];
        } else {
            S = g_xS[par][b][n];
            R = g_xR[par][b][n];
        }
        float Iv = I_s[n];

        float Npop = fmaxf(S + Iv + R, EPSV);
        float dS = -((beta * S) / Npop) * infection;
        float gI = gamma * Iv;
        float St = fmaxf(S + dS, 0.0f);
        float It = fmaxf(Iv - dS - gI, 0.0f);
        float Rt = fmaxf(R + gI, 0.0f);
        float scale = Npop / fmaxf(St + It + Rt, EPSV);
        St *= scale;
        It *= scale;
        Rt *= scale;

        if (lane == 0) {
            const int wpar = par ^ 1;
            g_xS[wpar][b][n] = St;
            g_xI[wpar][b][n] = It;
            g_xR[wpar][b][n] = Rt;
            float* orow = outv + rindex * 3;
            orow[0] = St;
            orow[1] = It;
            orow[2] = Rt;
        }

        // Prefetch next step's params row BEFORE the barrier so DRAM latency
        // overlaps the barrier wait.
        float2 vn[8];
        float p01n = 0.0f;
        if (t + 1 < TT) {
            load_row(params, rbase + (size_t)(t + 1) * NN, lane, vn, p01n);
        }

        group_barrier(b, (unsigned)(t + 1));

#pragma unroll
        for (int k = 0; k < 8; ++k) v[k] = vn[k];
        p01 = p01n;
    }
}

extern "C" void kernel_launch(void* const* d_in, const int* in_sizes, int n_in,
                              void* d_out, int out_size) {
    (void)in_sizes; (void)n_in; (void)out_size;
    const float* x0     = (const float*)d_in[0];
    const float* params = (const float*)d_in[1];
    float* out = (float*)d_out;

    reset_kernel<<<1, 32>>>();

    dim3 grid(BLOCKS_PER_GROUP, BB);
    ssir_kernel<<<grid, THREADS>>>(x0, params, out);
}

// round 9
// speedup vs baseline: 1.1796x; 1.1796x over previous
#include <cuda_runtime.h>
#include <cstdint>

// Shapes:
//   x0:     (B=4, N=512, 3)          float32
//   params: (B=4, T=96, N=512, 514)  float32
// d_out = output_view (B,T,N,3) ++ epiparams (B,T,N,514)

#define BB 4
#define TT 96
#define NN 512
#define PROW 514
#define EPSV 1e-8f

#define BLOCKS_PER_GROUP 32
#define THREADS 512
#define WARPS 16
#define OUT_VIEW_ELEMS (BB * TT * NN * 3)   // 589824

// ---- global scratch (static; no allocation) ----
__device__ unsigned g_count[BB];
__device__ unsigned g_release[BB];
__device__ float g_xI[2][BB][NN];   // double-buffered infected vector

__global__ void reset_kernel() {
    if (threadIdx.x < BB) {
        g_count[threadIdx.x]   = 0u;
        g_release[threadIdx.x] = 0u;
    }
}

__device__ __forceinline__ void load_row(const float* __restrict__ params,
                                         size_t rindex, int lane,
                                         float2 v[8], float& p01) {
    const float* prow = params + rindex * (size_t)PROW;
    p01 = (lane < 2) ? prow[lane] : 0.0f;
    // prow+2 is 8-byte aligned for every row (row stride 2056 B, +8).
    const float2* prow2 = reinterpret_cast<const float2*>(prow + 2);
#pragma unroll
    for (int k = 0; k < 8; ++k) v[k] = prow2[lane + 32 * k];
}

__global__ void __launch_bounds__(THREADS, 1)
ssir_kernel(const float* __restrict__ x0,
            const float* __restrict__ params,
            float* __restrict__ out) {
    __shared__ float I_s[NN];
    float2* I_s2 = reinterpret_cast<float2*>(I_s);

    const int b    = blockIdx.y;
    const int warp = threadIdx.x >> 5;
    const int lane = threadIdx.x & 31;
    const int n    = blockIdx.x * WARPS + warp;   // row owned by this warp

    float* outv = out;                   // output_view region
    float* oute = out + OUT_VIEW_ELEMS;  // epiparams region

    const size_t rbase = ((size_t)b * TT) * NN + (size_t)n;

    // Scan state lives in registers (redundant across lanes).
    const float* xr = x0 + ((size_t)b * NN + n) * 3;
    float S  = xr[0];
    float Iv = xr[1];
    float R  = xr[2];

    // Prefetch t=0 params row.
    float2 v[8];
    float p01;
    load_row(params, rbase, lane, v, p01);

    for (int t = 0; t < TT; ++t) {
        // ---------- SHADOW WORK (scan-independent) ----------
        float p0 = __shfl_sync(0xffffffffu, p01, 0);
        float p1 = __shfl_sync(0xffffffffu, p01, 1);
        float beta  = 1.0f / (1.0f + __expf(-p0));
        float gamma = 1.0f / (1.0f + __expf(-p1));

        float m = -1e30f;
#pragma unroll
        for (int k = 0; k < 8; ++k) m = fmaxf(m, fmaxf(v[k].x, v[k].y));
#pragma unroll
        for (int off = 16; off; off >>= 1)
            m = fmaxf(m, __shfl_xor_sync(0xffffffffu, m, off));

        float sum = 0.0f;
#pragma unroll
        for (int k = 0; k < 8; ++k) {
            v[k].x = __expf(v[k].x - m);
            v[k].y = __expf(v[k].y - m);
            sum += v[k].x + v[k].y;
        }
#pragma unroll
        for (int off = 16; off; off >>= 1)
            sum += __shfl_xor_sync(0xffffffffu, sum, off);
        float inv = 1.0f / sum;
#pragma unroll
        for (int k = 0; k < 8; ++k) { v[k].x *= inv; v[k].y *= inv; }

        // Prefetch next params row (issued before the barrier wait so DRAM
        // latency is absorbed by the wait).
        float2 vn[8];
        float p01n = 0.0f;
        if (t + 1 < TT)
            load_row(params, rbase + (size_t)(t + 1) * NN, lane, vn, p01n);

        // Stream out the epiparams row (independent of the scan).
        const size_t rindex = rbase + (size_t)t * NN;
        float* erow = oute + rindex * (size_t)PROW;
        if (lane == 0)
            *reinterpret_cast<float2*>(erow) = make_float2(beta, gamma);
        float2* erow2 = reinterpret_cast<float2*>(erow + 2);
#pragma unroll
        for (int k = 0; k < 8; ++k)
            erow2[lane + 32 * k] = v[k];

        // ---------- CRITICAL PATH ----------
        if (t > 0) {
            if (threadIdx.x == 0) {
                unsigned r;
                for (;;) {
                    asm volatile("ld.acquire.gpu.global.u32 %0, [%1];"
                                 : "=r"(r) : "l"(&g_release[b]) : "memory");
                    if (r >= (unsigned)t) break;
                    __nanosleep(20);
                }
            }
            __syncthreads();
            I_s[threadIdx.x] = g_xI[t & 1][b][threadIdx.x];
        } else {
            I_s[threadIdx.x] = x0[((size_t)b * NN + threadIdx.x) * 3 + 1];
        }
        __syncthreads();

        // infection_n = c_n . I_t  (softmax already normalized in v)
        float dot = 0.0f;
#pragma unroll
        for (int k = 0; k < 8; ++k) {
            float2 iv = I_s2[lane + 32 * k];
            dot += v[k].x * iv.x + v[k].y * iv.y;
        }
#pragma unroll
        for (int off = 16; off; off >>= 1)
            dot += __shfl_xor_sync(0xffffffffu, dot, off);
        float infection = dot;

        float Npop = fmaxf(S + Iv + R, EPSV);
        float dS = -((beta * S) / Npop) * infection;
        float gI = gamma * Iv;
        float St = fmaxf(S + dS, 0.0f);
        float It = fmaxf(Iv - dS - gI, 0.0f);
        float Rt = fmaxf(R + gI, 0.0f);
        float scale = Npop / fmaxf(St + It + Rt, EPSV);
        S  = St * scale;
        Iv = It * scale;
        R  = Rt * scale;

        if (lane == 0) {
            float* orow = outv + rindex * 3;
            orow[0] = S;
            orow[1] = Iv;
            orow[2] = Rt * scale;
            if (t + 1 < TT)
                g_xI[(t + 1) & 1][b][n] = Iv;
        }

        if (t + 1 < TT) {
            __syncthreads();                 // all warps' I writes issued
            if (threadIdx.x == 0) {
                __threadfence();             // publish I_{t+1}
                unsigned a = atomicAdd(&g_count[b], 1u) + 1u;
                if (a == (unsigned)(t + 1) * (unsigned)BLOCKS_PER_GROUP) {
                    __threadfence();
                    atomicExch(&g_release[b], (unsigned)(t + 1));
                }
            }
        }

#pragma unroll
        for (int k = 0; k < 8; ++k) v[k] = vn[k];
        p01 = p01n;
    }
}

extern "C" void kernel_launch(void* const* d_in, const int* in_sizes, int n_in,
                              void* d_out, int out_size) {
    (void)in_sizes; (void)n_in; (void)out_size;
    const float* x0     = (const float*)d_in[0];
    const float* params = (const float*)d_in[1];
    float* out = (float*)d_out;

    reset_kernel<<<1, 32>>>();

    dim3 grid(BLOCKS_PER_GROUP, BB);
    ssir_kernel<<<grid, THREADS>>>(x0, params, out);
}